// round 9
// baseline (speedup 1.0000x reference)
#include <cuda_runtime.h>
#include <math.h>
#include <stdint.h>

#define D_MODEL 1024
#define NHEADS  16
#define DK      64
#define BATCH   2
#define SEQ     2048
#define BS_TOK  (BATCH * SEQ)   // 4096 tokens

// ---------------------------------------------------------------------------
// Scratch (device globals: no allocation allowed)
// ---------------------------------------------------------------------------
__device__ float g_IQr[BS_TOK * D_MODEL];   // tf32-rounded inputs
__device__ float g_IKr[BS_TOK * D_MODEL];
__device__ float g_IVr[BS_TOK * D_MODEL];
__device__ float g_Wqt[D_MODEL * D_MODEL];  // tf32-rounded, transposed [n][k]
__device__ float g_Wkt[DK * D_MODEL];
__device__ float g_Wvt[DK * D_MODEL];
__device__ float g_Wot[D_MODEL * D_MODEL];
__device__ float g_Q[BS_TOK * D_MODEL];     // pre-scaled (1/8) + tf32-rounded
__device__ float g_K[BS_TOK * DK];          // tf32-rounded, [b*S+s][dk]
__device__ float g_Vt[BS_TOK * DK];         // tf32-rounded, transposed [b][dv][s]
__device__ float g_Ctx[BS_TOK * D_MODEL];   // tf32-rounded

// ---------------------------------------------------------------------------
// tf32 / cp.async / ldmatrix helpers
// ---------------------------------------------------------------------------
__device__ __forceinline__ unsigned f2tf(float x) {
    unsigned r;
    asm("cvt.rna.tf32.f32 %0, %1;" : "=r"(r) : "f"(x));
    return r;
}
__device__ __forceinline__ float f2tff(float x) {
    return __uint_as_float(f2tf(x));
}

__device__ __forceinline__ void cpa16(unsigned dst, const void* src) {
    asm volatile("cp.async.cg.shared.global [%0], [%1], 16;"
                 :: "r"(dst), "l"(src));
}
#define CP_COMMIT() asm volatile("cp.async.commit_group;" ::: "memory")
#define CP_WAIT0()  asm volatile("cp.async.wait_group 0;" ::: "memory")

__device__ __forceinline__ void ldsm4(unsigned* r, unsigned addr) {
    asm volatile("ldmatrix.sync.aligned.m8n8.x4.shared.b16 {%0,%1,%2,%3}, [%4];"
                 : "=r"(r[0]), "=r"(r[1]), "=r"(r[2]), "=r"(r[3]) : "r"(addr));
}

__device__ __forceinline__ void mma8(float* c, const unsigned* a,
                                     unsigned b0, unsigned b1) {
    asm volatile(
        "mma.sync.aligned.m16n8k8.row.col.f32.tf32.tf32.f32 "
        "{%0,%1,%2,%3}, {%4,%5,%6,%7}, {%8,%9}, {%0,%1,%2,%3};"
        : "+f"(c[0]), "+f"(c[1]), "+f"(c[2]), "+f"(c[3])
        : "r"(a[0]), "r"(a[1]), "r"(a[2]), "r"(a[3]), "r"(b0), "r"(b1));
}

// ---------------------------------------------------------------------------
// Prep: round the three inputs to tf32 bits (elementwise)
// ---------------------------------------------------------------------------
__global__ void round3(const float* __restrict__ a, const float* __restrict__ b,
                       const float* __restrict__ c, float* __restrict__ oa,
                       float* __restrict__ ob, float* __restrict__ oc, int n4)
{
    for (int i = blockIdx.x * blockDim.x + threadIdx.x; i < n4;
         i += gridDim.x * blockDim.x) {
        float4 v = ((const float4*)a)[i];
        ((float4*)oa)[i] = make_float4(f2tff(v.x), f2tff(v.y), f2tff(v.z), f2tff(v.w));
        v = ((const float4*)b)[i];
        ((float4*)ob)[i] = make_float4(f2tff(v.x), f2tff(v.y), f2tff(v.z), f2tff(v.w));
        v = ((const float4*)c)[i];
        ((float4*)oc)[i] = make_float4(f2tff(v.x), f2tff(v.y), f2tff(v.z), f2tff(v.w));
    }
}

// Prep: Wt[n][k] = rna(W[k][n]); K x N -> N x K. block (32,8), grid (N/32, K/32)
__global__ void trW(const float* __restrict__ W, float* __restrict__ Wt,
                    int K, int N)
{
    __shared__ float tl[32][33];
    int bx = blockIdx.x * 32, by = blockIdx.y * 32;
    int tx = threadIdx.x, ty = threadIdx.y;
    #pragma unroll
    for (int i = 0; i < 4; ++i)
        tl[ty + i * 8][tx] = f2tff(W[(size_t)(by + ty + i * 8) * N + bx + tx]);
    __syncthreads();
    #pragma unroll
    for (int i = 0; i < 4; ++i)
        Wt[(size_t)(bx + ty + i * 8) * K + by + tx] = tl[tx][ty + i * 8];
}

// ---------------------------------------------------------------------------
// Tensor-core GEMM, cp.async double-buffered, all fragments via ldmatrix.
// A [M,K] row-major (tf32 bits), Wt [N,K] row-major (tf32 bits).
// 8 warps as (BM/WM) x (BN/WN); WM = BM*(BN/WN)/8 = 64 in all configs.
// OMODE: 0 plain, 1 rtf, 2 rtf*0.125, 3 rtf + transposed V write.
// ---------------------------------------------------------------------------
template<int BM, int BN, int WN, int OMODE>
__device__ __forceinline__
void gemm_body(const float* __restrict__ A, const float* __restrict__ Wt,
               const float* __restrict__ bias, float* __restrict__ C,
               int N, int K, int m0, int n0)
{
    constexpr int ASTR = 36;
    constexpr int ABUF = BM * ASTR;
    constexpr int BBUF = BN * ASTR;
    constexpr int NF = WN / 8;
    constexpr int NWC = BN / WN;          // warp cols
    constexpr int ACH = BM / 32;          // cp.async chunks per thread (A)
    constexpr int BCH = BN / 32;          // cp.async chunks per thread (B)
    extern __shared__ unsigned smg[];
    const unsigned sb = (unsigned)__cvta_generic_to_shared(smg);

    const int t = threadIdx.x, lane = t & 31, wp = t >> 5;
    const int wm0 = (wp / NWC) * 64, wn0 = (wp % NWC) * WN;
    const int gid = lane >> 2, tig = lane & 3;

    const int m4 = lane >> 3, j8 = lane & 7;
    const unsigned a_loff = (unsigned)((((m4 & 1) * 8 + j8) * ASTR +
                                        (m4 >> 1) * 4) * 4);
    const unsigned b_loff = (unsigned)((((m4 >> 1) * 8 + j8) * ASTR +
                                        (m4 & 1) * 4) * 4);

    // ---- prologue: stage tile 0 into buffers 0 ----
    #pragma unroll
    for (int i = 0; i < ACH; ++i) {
        int idx = t + 256 * i;
        int r = idx >> 3, c4 = (idx & 7) * 4;
        cpa16(sb + (unsigned)((r * ASTR + c4) * 4),
              A + (size_t)(m0 + r) * K + c4);
    }
    #pragma unroll
    for (int i = 0; i < BCH; ++i) {
        int idx = t + 256 * i;
        int r = idx >> 3, c4 = (idx & 7) * 4;
        cpa16(sb + (unsigned)((2 * ABUF + r * ASTR + c4) * 4),
              Wt + (size_t)(n0 + r) * K + c4);
    }
    CP_COMMIT();

    float acc[4][NF][4];
    #pragma unroll
    for (int mi = 0; mi < 4; ++mi)
        #pragma unroll
        for (int ni = 0; ni < NF; ++ni)
            #pragma unroll
            for (int x = 0; x < 4; ++x) acc[mi][ni][x] = 0.0f;

    int cur = 0;
    for (int k0 = 0; k0 < K; k0 += 32) {
        CP_WAIT0();
        __syncthreads();

        if (k0 + 32 < K) {
            const unsigned ao = (unsigned)((cur ^ 1) * ABUF * 4);
            const unsigned bo = (unsigned)((2 * ABUF + (cur ^ 1) * BBUF) * 4);
            #pragma unroll
            for (int i = 0; i < ACH; ++i) {
                int idx = t + 256 * i;
                int r = idx >> 3, c4 = (idx & 7) * 4;
                cpa16(sb + ao + (unsigned)((r * ASTR + c4) * 4),
                      A + (size_t)(m0 + r) * K + k0 + 32 + c4);
            }
            #pragma unroll
            for (int i = 0; i < BCH; ++i) {
                int idx = t + 256 * i;
                int r = idx >> 3, c4 = (idx & 7) * 4;
                cpa16(sb + bo + (unsigned)((r * ASTR + c4) * 4),
                      Wt + (size_t)(n0 + r) * K + k0 + 32 + c4);
            }
            CP_COMMIT();
        }

        const unsigned asb = sb + (unsigned)(cur * ABUF * 4) +
                             (unsigned)(wm0 * ASTR * 4) + a_loff;
        const unsigned bsb = sb + (unsigned)((2 * ABUF + cur * BBUF) * 4) +
                             (unsigned)(wn0 * ASTR * 4) + b_loff;

        #pragma unroll
        for (int kk = 0; kk < 4; ++kk) {
            unsigned a[4][4];
            #pragma unroll
            for (int mi = 0; mi < 4; ++mi)
                ldsm4(a[mi], asb + (unsigned)(mi * 16 * ASTR * 4 + kk * 32));
            #pragma unroll
            for (int nfp = 0; nfp < NF / 2; ++nfp) {
                unsigned bb[4];
                ldsm4(bb, bsb + (unsigned)(nfp * 16 * ASTR * 4 + kk * 32));
                #pragma unroll
                for (int mi = 0; mi < 4; ++mi) {
                    mma8(acc[mi][2 * nfp],     a[mi], bb[0], bb[1]);
                    mma8(acc[mi][2 * nfp + 1], a[mi], bb[2], bb[3]);
                }
            }
        }
        cur ^= 1;
    }

    // ---- epilogue ----
    #pragma unroll
    for (int mi = 0; mi < 4; ++mi) {
        int r = m0 + wm0 + mi * 16 + gid;
        #pragma unroll
        for (int ni = 0; ni < NF; ++ni) {
            int c = n0 + wn0 + ni * 8 + 2 * tig;
            float bb0 = bias[c], bb1 = bias[c + 1];
            float o0 = acc[mi][ni][0] + bb0, o1 = acc[mi][ni][1] + bb1;
            float o2 = acc[mi][ni][2] + bb0, o3 = acc[mi][ni][3] + bb1;
            if (OMODE == 2) {
                o0 = f2tff(0.125f * o0); o1 = f2tff(0.125f * o1);
                o2 = f2tff(0.125f * o2); o3 = f2tff(0.125f * o3);
            } else if (OMODE == 1 || OMODE == 3) {
                o0 = f2tff(o0); o1 = f2tff(o1);
                o2 = f2tff(o2); o3 = f2tff(o3);
            }
            if (OMODE == 3) {
                int bb_ = r >> 11, ss = r & (SEQ - 1);
                C[((size_t)(bb_ * DK + c))     * SEQ + ss]     = o0;
                C[((size_t)(bb_ * DK + c + 1)) * SEQ + ss]     = o1;
                C[((size_t)(bb_ * DK + c))     * SEQ + ss + 8] = o2;
                C[((size_t)(bb_ * DK + c + 1)) * SEQ + ss + 8] = o3;
            } else {
                *(float2*)&C[(size_t)r * N + c] = make_float2(o0, o1);
                *(float2*)&C[(size_t)(r + 8) * N + c] = make_float2(o2, o3);
            }
        }
    }
}

// Big projections: 256x128 CTA tile, warp tile 64x64 -> 128 CTAs (one wave)
__global__ __launch_bounds__(256)
void gemm_q(const float* __restrict__ A, const float* __restrict__ Wt,
            const float* __restrict__ bias, float* __restrict__ C)
{
    gemm_body<256, 128, 64, 2>(A, Wt, bias, C, D_MODEL, D_MODEL,
                               blockIdx.y * 256, blockIdx.x * 128);
}

__global__ __launch_bounds__(256)
void gemm_o(const float* __restrict__ A, const float* __restrict__ Wt,
            const float* __restrict__ bias, float* __restrict__ C)
{
    gemm_body<256, 128, 64, 0>(A, Wt, bias, C, D_MODEL, D_MODEL,
                               blockIdx.y * 256, blockIdx.x * 128);
}

__global__ __launch_bounds__(256)
void gemm_kv(const float* __restrict__ Ak, const float* __restrict__ Wkt,
             const float* __restrict__ bk, float* __restrict__ Ck,
             const float* __restrict__ Av, const float* __restrict__ Wvt,
             const float* __restrict__ bv, float* __restrict__ Cv)
{
    if (blockIdx.z == 0)
        gemm_body<128, 64, 16, 1>(Ak, Wkt, bk, Ck, DK, D_MODEL,
                                  blockIdx.y * 128, 0);
    else
        gemm_body<128, 64, 16, 3>(Av, Wvt, bv, Cv, DK, D_MODEL,
                                  blockIdx.y * 128, 0);
}

#define GEMM_SMEM_BIG ((2 * 256 * 36 + 2 * 128 * 36) * 4)   // 110592
#define GEMM_SMEM_64  ((2 * 128 * 36 + 2 * 64 * 36) * 4)    // 55296

// ---------------------------------------------------------------------------
// Flash attention (MQA, causal), 2 heads/CTA, merged MMA bursts, cp.async
// staging for Q, K and Vt (all pre-rounded/pre-scaled tf32 bits).
// ---------------------------------------------------------------------------
#define AS 68
#define ATTN_SMEM_TC ((4 * 64 + 128) * AS * 4)   // 104448 B

__global__ __launch_bounds__(256)
void attn_tc(const float* __restrict__ Q, const float* __restrict__ K,
             const float* __restrict__ Vt, float* __restrict__ Ctx)
{
    extern __shared__ unsigned smu[];
    const unsigned sb = (unsigned)__cvta_generic_to_shared(smu);
    unsigned* Ps = smu + 4 * 64 * AS;
    const unsigned ps_base = sb + (unsigned)(4 * 64 * AS * 4);

    const int t = threadIdx.x, lane = t & 31, w = t >> 5;
    const int hw = w & 3;
    const int gid = lane >> 2, tig = lane & 3;
    const int qt = (int)(gridDim.x - 1) - (int)blockIdx.x;  // long blocks first
    const int h = blockIdx.y * 2 + (w >> 2);
    const int b = blockIdx.z;

    const int m4 = lane >> 3, j8 = lane & 7;
    const unsigned a_loff = (unsigned)((((m4 & 1) * 8 + j8) * AS +
                                        (m4 >> 1) * 4) * 4);
    const unsigned b_loff = (unsigned)((((m4 >> 1) * 8 + j8) * AS +
                                        (m4 & 1) * 4) * 4);

    // ---- preloop: cp.async K0 (+K1), V0, and Q (both heads) ----
    {
        #pragma unroll
        for (int ld = 0; ld < 4; ++ld) {
            int i = t + 256 * ld;
            int row = i >> 4, c4 = (i & 15) * 4;
            unsigned so = (unsigned)(row * AS + c4) * 4u;
            cpa16(sb + so, K + ((size_t)(b * SEQ + row)) * DK + c4);
            if (qt >= 1)
                cpa16(sb + (64 * AS) * 4u + so,
                      K + ((size_t)(b * SEQ + 64 + row)) * DK + c4);
            cpa16(sb + (2 * 64 * AS) * 4u + so,
                  Vt + ((size_t)(b * DK + row)) * SEQ + c4);
        }
        #pragma unroll
        for (int ld = 0; ld < 8; ++ld) {
            int i = t + 256 * ld;
            int row = i >> 4, c4 = (i & 15) * 4;
            int hh = blockIdx.y * 2 + (row >> 6);
            int qrow = row & 63;
            cpa16(ps_base + (unsigned)(row * AS + c4) * 4u,
                  Q + ((size_t)(b * SEQ + qt * 64 + qrow)) * D_MODEL
                    + hh * DK + c4);
        }
        CP_COMMIT();
    }
    CP_WAIT0();
    __syncthreads();

    const unsigned ps_warp = ps_base + (unsigned)(16 * w * AS * 4);
    unsigned Qa[8][4];
    #pragma unroll
    for (int kf = 0; kf < 8; ++kf)
        ldsm4(Qa[kf], ps_warp + a_loff + kf * 32);

    float m0 = -INFINITY, m1 = -INFINITY, l0 = 0.0f, l1 = 0.0f;
    float O[8][4], S[8][4];
    #pragma unroll
    for (int nf = 0; nf < 8; ++nf)
        #pragma unroll
        for (int x = 0; x < 4; ++x) { O[nf][x] = 0.0f; S[nf][x] = 0.0f; }

    // ---- QK(0) from stage 0 ----
    #pragma unroll
    for (int kf = 0; kf < 8; ++kf) {
        #pragma unroll
        for (int nfp = 0; nfp < 4; ++nfp) {
            unsigned bb[4];
            ldsm4(bb, sb + (unsigned)(nfp * 16 * AS * 4) + b_loff + kf * 32);
            mma8(S[2 * nfp],     Qa[kf], bb[0], bb[1]);
            mma8(S[2 * nfp + 1], Qa[kf], bb[2], bb[3]);
        }
    }

    for (int j = 0; j <= qt; ++j) {
        CP_WAIT0();
        __syncthreads();

        // ---- prefetch K(j+2) -> stage j%2, V(j+1) -> stage (j+1)%2 ----
        {
            const unsigned ko = (unsigned)((j & 1) * 64 * AS) * 4u;
            const unsigned vo = (unsigned)((2 + ((j + 1) & 1)) * 64 * AS) * 4u;
            #pragma unroll
            for (int ld = 0; ld < 4; ++ld) {
                int i = t + 256 * ld;
                int row = i >> 4, c4 = (i & 15) * 4;
                unsigned so = (unsigned)(row * AS + c4) * 4u;
                if (j + 2 <= qt)
                    cpa16(sb + ko + so,
                          K + ((size_t)(b * SEQ + (j + 2) * 64 + row)) * DK + c4);
                if (j + 1 <= qt)
                    cpa16(sb + vo + so,
                          Vt + ((size_t)(b * DK + row)) * SEQ + (j + 1) * 64 + c4);
            }
            CP_COMMIT();
        }

        // ---- softmax on S (tile j) ----
        if (j == qt) {
            int qr = qt * 64 + 16 * hw + gid;
            #pragma unroll
            for (int nf = 0; nf < 8; ++nf) {
                int c0 = j * 64 + nf * 8 + 2 * tig;
                if (c0     > qr)     S[nf][0] = -INFINITY;
                if (c0 + 1 > qr)     S[nf][1] = -INFINITY;
                if (c0     > qr + 8) S[nf][2] = -INFINITY;
                if (c0 + 1 > qr + 8) S[nf][3] = -INFINITY;
            }
        }
        float mx0 = -INFINITY, mx1 = -INFINITY;
        #pragma unroll
        for (int nf = 0; nf < 8; ++nf) {
            mx0 = fmaxf(mx0, fmaxf(S[nf][0], S[nf][1]));
            mx1 = fmaxf(mx1, fmaxf(S[nf][2], S[nf][3]));
        }
        mx0 = fmaxf(mx0, __shfl_xor_sync(0xffffffffu, mx0, 1));
        mx0 = fmaxf(mx0, __shfl_xor_sync(0xffffffffu, mx0, 2));
        mx1 = fmaxf(mx1, __shfl_xor_sync(0xffffffffu, mx1, 1));
        mx1 = fmaxf(mx1, __shfl_xor_sync(0xffffffffu, mx1, 2));

        float mn0 = fmaxf(m0, mx0), mn1 = fmaxf(m1, mx1);
        float cr0 = __expf(m0 - mn0), cr1 = __expf(m1 - mn1);
        m0 = mn0; m1 = mn1;

        float rs0 = 0.0f, rs1 = 0.0f;
        #pragma unroll
        for (int nf = 0; nf < 8; ++nf) {
            S[nf][0] = __expf(S[nf][0] - mn0);
            S[nf][1] = __expf(S[nf][1] - mn0);
            S[nf][2] = __expf(S[nf][2] - mn1);
            S[nf][3] = __expf(S[nf][3] - mn1);
            rs0 += S[nf][0] + S[nf][1];
            rs1 += S[nf][2] + S[nf][3];
        }
        rs0 += __shfl_xor_sync(0xffffffffu, rs0, 1);
        rs0 += __shfl_xor_sync(0xffffffffu, rs0, 2);
        rs1 += __shfl_xor_sync(0xffffffffu, rs1, 1);
        rs1 += __shfl_xor_sync(0xffffffffu, rs1, 2);
        l0 = l0 * cr0 + rs0;
        l1 = l1 * cr1 + rs1;
        #pragma unroll
        for (int nf = 0; nf < 8; ++nf) {
            O[nf][0] *= cr0; O[nf][1] *= cr0;
            O[nf][2] *= cr1; O[nf][3] *= cr1;
        }

        // ---- P -> smem (warp-private rows), free S for tile j+1 ----
        const int pr = 16 * w + gid;
        #pragma unroll
        for (int nf = 0; nf < 8; ++nf) {
            int pc = nf * 8 + 2 * tig;
            *(uint2*)&Ps[pr * AS + pc] =
                make_uint2(f2tf(S[nf][0]), f2tf(S[nf][1]));
            *(uint2*)&Ps[(pr + 8) * AS + pc] =
                make_uint2(f2tf(S[nf][2]), f2tf(S[nf][3]));
            S[nf][0] = 0.0f; S[nf][1] = 0.0f; S[nf][2] = 0.0f; S[nf][3] = 0.0f;
        }
        __syncwarp();

        // ---- merged burst: QK(j+1) + PV(j) ----
        const unsigned ksb = sb + (unsigned)((((j + 1) & 1)) * 64 * AS * 4);
        const unsigned vtb = sb + (unsigned)((2 + (j & 1)) * 64 * AS * 4);
        if (j < qt) {
            #pragma unroll
            for (int kf = 0; kf < 8; ++kf) {
                unsigned pa[4];
                ldsm4(pa, ps_warp + a_loff + kf * 32);
                #pragma unroll
                for (int nfp = 0; nfp < 4; ++nfp) {
                    unsigned kb[4];
                    ldsm4(kb, ksb + (unsigned)(nfp * 16 * AS * 4) + b_loff
                              + kf * 32);
                    mma8(S[2 * nfp],     Qa[kf], kb[0], kb[1]);
                    mma8(S[2 * nfp + 1], Qa[kf], kb[2], kb[3]);
                }
                #pragma unroll
                for (int nfp = 0; nfp < 4; ++nfp) {
                    unsigned vb[4];
                    ldsm4(vb, vtb + (unsigned)(nfp * 16 * AS * 4) + b_loff
                              + kf * 32);
                    mma8(O[2 * nfp],     pa, vb[0], vb[1]);
                    mma8(O[2 * nfp + 1], pa, vb[2], vb[3]);
                }
            }
        } else {
            #pragma unroll
            for (int kf = 0; kf < 8; ++kf) {
                unsigned pa[4];
                ldsm4(pa, ps_warp + a_loff + kf * 32);
                #pragma unroll
                for (int nfp = 0; nfp < 4; ++nfp) {
                    unsigned vb[4];
                    ldsm4(vb, vtb + (unsigned)(nfp * 16 * AS * 4) + b_loff
                              + kf * 32);
                    mma8(O[2 * nfp],     pa, vb[0], vb[1]);
                    mma8(O[2 * nfp + 1], pa, vb[2], vb[3]);
                }
            }
        }
    }

    // ---- normalize + write context (tf32-rounded for the O projection) ----
    float inv0 = 1.0f / l0, inv1 = 1.0f / l1;
    int r0 = qt * 64 + 16 * hw + gid;
    #pragma unroll
    for (int nf = 0; nf < 8; ++nf) {
        int c = h * DK + nf * 8 + 2 * tig;
        *(float2*)&Ctx[((size_t)(b * SEQ + r0)) * D_MODEL + c] =
            make_float2(f2tff(O[nf][0] * inv0), f2tff(O[nf][1] * inv0));
        *(float2*)&Ctx[((size_t)(b * SEQ + r0 + 8)) * D_MODEL + c] =
            make_float2(f2tff(O[nf][2] * inv1), f2tff(O[nf][3] * inv1));
    }
}

// ---------------------------------------------------------------------------
// launch
// ---------------------------------------------------------------------------
extern "C" void kernel_launch(void* const* d_in, const int* in_sizes, int n_in,
                              void* d_out, int out_size)
{
    const float* iq = (const float*)d_in[0];
    const float* ik = (const float*)d_in[1];
    const float* iv = (const float*)d_in[2];
    const float* Wq = (const float*)d_in[3];
    const float* bq = (const float*)d_in[4];
    const float* Wk = (const float*)d_in[5];
    const float* bk = (const float*)d_in[6];
    const float* Wv = (const float*)d_in[7];
    const float* bv = (const float*)d_in[8];
    const float* Wo = (const float*)d_in[9];
    const float* bo = (const float*)d_in[10];
    float* out = (float*)d_out;

    float *pIQ, *pIK, *pIV, *pWqt, *pWkt, *pWvt, *pWot;
    float *pQ, *pK, *pVt, *pCtx;
    cudaGetSymbolAddress((void**)&pIQ,  g_IQr);
    cudaGetSymbolAddress((void**)&pIK,  g_IKr);
    cudaGetSymbolAddress((void**)&pIV,  g_IVr);
    cudaGetSymbolAddress((void**)&pWqt, g_Wqt);
    cudaGetSymbolAddress((void**)&pWkt, g_Wkt);
    cudaGetSymbolAddress((void**)&pWvt, g_Wvt);
    cudaGetSymbolAddress((void**)&pWot, g_Wot);
    cudaGetSymbolAddress((void**)&pQ,   g_Q);
    cudaGetSymbolAddress((void**)&pK,   g_K);
    cudaGetSymbolAddress((void**)&pVt,  g_Vt);
    cudaGetSymbolAddress((void**)&pCtx, g_Ctx);

    cudaFuncSetAttribute((const void*)gemm_q,
                         cudaFuncAttributeMaxDynamicSharedMemorySize,
                         GEMM_SMEM_BIG);
    cudaFuncSetAttribute((const void*)gemm_o,
                         cudaFuncAttributeMaxDynamicSharedMemorySize,
                         GEMM_SMEM_BIG);
    cudaFuncSetAttribute((const void*)gemm_kv,
                         cudaFuncAttributeMaxDynamicSharedMemorySize,
                         GEMM_SMEM_64);
    cudaFuncSetAttribute((const void*)attn_tc,
                         cudaFuncAttributeMaxDynamicSharedMemorySize,
                         ATTN_SMEM_TC);

    // ---- prep: round inputs, round+transpose weights ----
    round3<<<1024, 256>>>(iq, ik, iv, pIQ, pIK, pIV,
                          BS_TOK * D_MODEL / 4);
    trW<<<dim3(D_MODEL / 32, D_MODEL / 32), dim3(32, 8)>>>(Wq, pWqt,
                                                           D_MODEL, D_MODEL);
    trW<<<dim3(DK / 32, D_MODEL / 32), dim3(32, 8)>>>(Wk, pWkt, D_MODEL, DK);
    trW<<<dim3(DK / 32, D_MODEL / 32), dim3(32, 8)>>>(Wv, pWvt, D_MODEL, DK);
    trW<<<dim3(D_MODEL / 32, D_MODEL / 32), dim3(32, 8)>>>(Wo, pWot,
                                                           D_MODEL, D_MODEL);

    // ---- K+V projections (z: 0=K row-major, 1=V transposed) ----
    gemm_kv<<<dim3(1, BS_TOK / 128, 2), 256, GEMM_SMEM_64>>>(
        pIK, pWkt, bk, pK, pIV, pWvt, bv, pVt);

    // ---- Q projection (output pre-scaled + rounded) ----
    gemm_q<<<dim3(D_MODEL / 128, BS_TOK / 256), 256, GEMM_SMEM_BIG>>>(
        pIQ, pWqt, bq, pQ);

    // ---- attention ----
    attn_tc<<<dim3(SEQ / 64, NHEADS / 2, BATCH), 256, ATTN_SMEM_TC>>>(
        pQ, pK, pVt, pCtx);

    // ---- output projection ----
    gemm_o<<<dim3(D_MODEL / 128, BS_TOK / 256), 256, GEMM_SMEM_BIG>>>(
        pCtx, pWot, bo, out);
}

// round 10
// speedup vs baseline: 1.0518x; 1.0518x over previous
#include <cuda_runtime.h>
#include <math.h>
#include <stdint.h>

#define D_MODEL 1024
#define NHEADS  16
#define DK      64
#define BATCH   2
#define SEQ     2048
#define BS_TOK  (BATCH * SEQ)   // 4096 tokens

// ---------------------------------------------------------------------------
// Scratch (device globals: no allocation allowed)
// ---------------------------------------------------------------------------
__device__ float g_IQr[BS_TOK * D_MODEL];   // tf32-rounded inputs
__device__ float g_IKr[BS_TOK * D_MODEL];
__device__ float g_IVr[BS_TOK * D_MODEL];
__device__ float g_Wqt[D_MODEL * D_MODEL];  // tf32-rounded, transposed [n][k]
__device__ float g_Wkt[DK * D_MODEL];
__device__ float g_Wvt[DK * D_MODEL];
__device__ float g_Wot[D_MODEL * D_MODEL];
__device__ float g_Q[BS_TOK * D_MODEL];     // pre-scaled (1/8) + tf32-rounded
__device__ float g_K[BS_TOK * DK];          // tf32-rounded, [b*S+s][dk]
__device__ float g_Vt[BS_TOK * DK];         // tf32-rounded, transposed [b][dv][s]
__device__ float g_Ctx[BS_TOK * D_MODEL];   // tf32-rounded

// ---------------------------------------------------------------------------
// tf32 / cp.async / ldmatrix helpers
// ---------------------------------------------------------------------------
__device__ __forceinline__ unsigned f2tf(float x) {
    unsigned r;
    asm("cvt.rna.tf32.f32 %0, %1;" : "=r"(r) : "f"(x));
    return r;
}
__device__ __forceinline__ float f2tff(float x) {
    return __uint_as_float(f2tf(x));
}

__device__ __forceinline__ void cpa16(unsigned dst, const void* src) {
    asm volatile("cp.async.cg.shared.global [%0], [%1], 16;"
                 :: "r"(dst), "l"(src));
}
#define CP_COMMIT() asm volatile("cp.async.commit_group;" ::: "memory")
#define CP_WAIT0()  asm volatile("cp.async.wait_group 0;" ::: "memory")

__device__ __forceinline__ void ldsm4(unsigned* r, unsigned addr) {
    asm volatile("ldmatrix.sync.aligned.m8n8.x4.shared.b16 {%0,%1,%2,%3}, [%4];"
                 : "=r"(r[0]), "=r"(r[1]), "=r"(r[2]), "=r"(r[3]) : "r"(addr));
}

__device__ __forceinline__ void mma8(float* c, const unsigned* a,
                                     unsigned b0, unsigned b1) {
    asm volatile(
        "mma.sync.aligned.m16n8k8.row.col.f32.tf32.tf32.f32 "
        "{%0,%1,%2,%3}, {%4,%5,%6,%7}, {%8,%9}, {%0,%1,%2,%3};"
        : "+f"(c[0]), "+f"(c[1]), "+f"(c[2]), "+f"(c[3])
        : "r"(a[0]), "r"(a[1]), "r"(a[2]), "r"(a[3]), "r"(b0), "r"(b1));
}

// ---------------------------------------------------------------------------
// Fused prep kernel: input rounding + all weight transposes, one launch.
// Block ranges: [0,768) round inputs; [768,1792) Wq; [1792,2816) Wo;
// [2816,2880) Wk; [2880,2944) Wv.
// ---------------------------------------------------------------------------
#define NB_R3 768
#define NB_WB 1024          // 32x32 for 1024x1024 weights
#define NB_WS 64            // (64/32)x(1024/32) for 1024x64 weights
#define NB_PREP (NB_R3 + 2 * NB_WB + 2 * NB_WS)   // 2944

__device__ __forceinline__
void trW_body(const float* __restrict__ W, float* __restrict__ Wt,
              int K, int N, int bid, int tid)
{
    __shared__ float tl[32][33];
    const int nbx = N / 32;
    const int bx = (bid % nbx) * 32, by = (bid / nbx) * 32;
    const int tx = tid & 31, ty = tid >> 5;
    #pragma unroll
    for (int i = 0; i < 4; ++i)
        tl[ty + i * 8][tx] = f2tff(W[(size_t)(by + ty + i * 8) * N + bx + tx]);
    __syncthreads();
    #pragma unroll
    for (int i = 0; i < 4; ++i)
        Wt[(size_t)(bx + ty + i * 8) * K + by + tx] = tl[tx][ty + i * 8];
}

__global__ __launch_bounds__(256)
void prep(const float* __restrict__ iq, const float* __restrict__ ik,
          const float* __restrict__ iv, float* __restrict__ oq,
          float* __restrict__ ok, float* __restrict__ ov,
          const float* __restrict__ Wq, float* __restrict__ Wqt,
          const float* __restrict__ Wo, float* __restrict__ Wot,
          const float* __restrict__ Wk, float* __restrict__ Wkt,
          const float* __restrict__ Wv, float* __restrict__ Wvt)
{
    const int blk = blockIdx.x, tid = threadIdx.x;
    if (blk < NB_R3) {
        const int n4 = BS_TOK * D_MODEL / 4;
        for (int i = blk * 256 + tid; i < n4; i += NB_R3 * 256) {
            float4 v = ((const float4*)iq)[i];
            ((float4*)oq)[i] = make_float4(f2tff(v.x), f2tff(v.y),
                                           f2tff(v.z), f2tff(v.w));
            v = ((const float4*)ik)[i];
            ((float4*)ok)[i] = make_float4(f2tff(v.x), f2tff(v.y),
                                           f2tff(v.z), f2tff(v.w));
            v = ((const float4*)iv)[i];
            ((float4*)ov)[i] = make_float4(f2tff(v.x), f2tff(v.y),
                                           f2tff(v.z), f2tff(v.w));
        }
    } else if (blk < NB_R3 + NB_WB) {
        trW_body(Wq, Wqt, D_MODEL, D_MODEL, blk - NB_R3, tid);
    } else if (blk < NB_R3 + 2 * NB_WB) {
        trW_body(Wo, Wot, D_MODEL, D_MODEL, blk - NB_R3 - NB_WB, tid);
    } else if (blk < NB_R3 + 2 * NB_WB + NB_WS) {
        trW_body(Wk, Wkt, D_MODEL, DK, blk - NB_R3 - 2 * NB_WB, tid);
    } else {
        trW_body(Wv, Wvt, D_MODEL, DK, blk - NB_R3 - 2 * NB_WB - NB_WS, tid);
    }
}

// ---------------------------------------------------------------------------
// Tensor-core GEMM body (round-8 config), cp.async double-buffered, ldmatrix.
// A [M,K] row-major (tf32 bits), Wt [N,K] row-major (tf32 bits).
// 8 warps as (BM/64) x (BN/WN). OMODE: 0 plain, 1 rtf, 2 rtf*0.125,
// 3 rtf + transposed V write.
// ---------------------------------------------------------------------------
template<int BM, int BN, int WN, int OMODE>
__device__ __forceinline__
void gemm_body(const float* __restrict__ A, const float* __restrict__ Wt,
               const float* __restrict__ bias, float* __restrict__ C,
               int N, int K, int m0, int n0)
{
    constexpr int ASTR = 36;
    constexpr int ABUF = BM * ASTR;
    constexpr int BBUF = BN * ASTR;
    constexpr int NF = WN / 8;
    constexpr int NWC = BN / WN;
    constexpr int ACH = BM / 32;
    constexpr int BCH = BN / 32;
    extern __shared__ unsigned smg[];
    const unsigned sb = (unsigned)__cvta_generic_to_shared(smg);

    const int t = threadIdx.x, lane = t & 31, wp = t >> 5;
    const int wm0 = (wp / NWC) * 64, wn0 = (wp % NWC) * WN;
    const int gid = lane >> 2, tig = lane & 3;

    const int m4 = lane >> 3, j8 = lane & 7;
    const unsigned a_loff = (unsigned)((((m4 & 1) * 8 + j8) * ASTR +
                                        (m4 >> 1) * 4) * 4);
    const unsigned b_loff = (unsigned)((((m4 >> 1) * 8 + j8) * ASTR +
                                        (m4 & 1) * 4) * 4);

    // ---- prologue: stage tile 0 into buffers 0 ----
    #pragma unroll
    for (int i = 0; i < ACH; ++i) {
        int idx = t + 256 * i;
        int r = idx >> 3, c4 = (idx & 7) * 4;
        cpa16(sb + (unsigned)((r * ASTR + c4) * 4),
              A + (size_t)(m0 + r) * K + c4);
    }
    #pragma unroll
    for (int i = 0; i < BCH; ++i) {
        int idx = t + 256 * i;
        int r = idx >> 3, c4 = (idx & 7) * 4;
        cpa16(sb + (unsigned)((2 * ABUF + r * ASTR + c4) * 4),
              Wt + (size_t)(n0 + r) * K + c4);
    }
    CP_COMMIT();

    float acc[4][NF][4];
    #pragma unroll
    for (int mi = 0; mi < 4; ++mi)
        #pragma unroll
        for (int ni = 0; ni < NF; ++ni)
            #pragma unroll
            for (int x = 0; x < 4; ++x) acc[mi][ni][x] = 0.0f;

    int cur = 0;
    for (int k0 = 0; k0 < K; k0 += 32) {
        CP_WAIT0();
        __syncthreads();

        if (k0 + 32 < K) {
            const unsigned ao = (unsigned)((cur ^ 1) * ABUF * 4);
            const unsigned bo = (unsigned)((2 * ABUF + (cur ^ 1) * BBUF) * 4);
            #pragma unroll
            for (int i = 0; i < ACH; ++i) {
                int idx = t + 256 * i;
                int r = idx >> 3, c4 = (idx & 7) * 4;
                cpa16(sb + ao + (unsigned)((r * ASTR + c4) * 4),
                      A + (size_t)(m0 + r) * K + k0 + 32 + c4);
            }
            #pragma unroll
            for (int i = 0; i < BCH; ++i) {
                int idx = t + 256 * i;
                int r = idx >> 3, c4 = (idx & 7) * 4;
                cpa16(sb + bo + (unsigned)((r * ASTR + c4) * 4),
                      Wt + (size_t)(n0 + r) * K + k0 + 32 + c4);
            }
            CP_COMMIT();
        }

        const unsigned asb = sb + (unsigned)(cur * ABUF * 4) +
                             (unsigned)(wm0 * ASTR * 4) + a_loff;
        const unsigned bsb = sb + (unsigned)((2 * ABUF + cur * BBUF) * 4) +
                             (unsigned)(wn0 * ASTR * 4) + b_loff;

        #pragma unroll
        for (int kk = 0; kk < 4; ++kk) {
            unsigned a[4][4];
            #pragma unroll
            for (int mi = 0; mi < 4; ++mi)
                ldsm4(a[mi], asb + (unsigned)(mi * 16 * ASTR * 4 + kk * 32));
            #pragma unroll
            for (int nfp = 0; nfp < NF / 2; ++nfp) {
                unsigned bb[4];
                ldsm4(bb, bsb + (unsigned)(nfp * 16 * ASTR * 4 + kk * 32));
                #pragma unroll
                for (int mi = 0; mi < 4; ++mi) {
                    mma8(acc[mi][2 * nfp],     a[mi], bb[0], bb[1]);
                    mma8(acc[mi][2 * nfp + 1], a[mi], bb[2], bb[3]);
                }
            }
        }
        cur ^= 1;
    }

    // ---- epilogue ----
    #pragma unroll
    for (int mi = 0; mi < 4; ++mi) {
        int r = m0 + wm0 + mi * 16 + gid;
        #pragma unroll
        for (int ni = 0; ni < NF; ++ni) {
            int c = n0 + wn0 + ni * 8 + 2 * tig;
            float bb0 = bias[c], bb1 = bias[c + 1];
            float o0 = acc[mi][ni][0] + bb0, o1 = acc[mi][ni][1] + bb1;
            float o2 = acc[mi][ni][2] + bb0, o3 = acc[mi][ni][3] + bb1;
            if (OMODE == 2) {
                o0 = f2tff(0.125f * o0); o1 = f2tff(0.125f * o1);
                o2 = f2tff(0.125f * o2); o3 = f2tff(0.125f * o3);
            } else if (OMODE == 1 || OMODE == 3) {
                o0 = f2tff(o0); o1 = f2tff(o1);
                o2 = f2tff(o2); o3 = f2tff(o3);
            }
            if (OMODE == 3) {
                int bb_ = r >> 11, ss = r & (SEQ - 1);
                C[((size_t)(bb_ * DK + c))     * SEQ + ss]     = o0;
                C[((size_t)(bb_ * DK + c + 1)) * SEQ + ss]     = o1;
                C[((size_t)(bb_ * DK + c))     * SEQ + ss + 8] = o2;
                C[((size_t)(bb_ * DK + c + 1)) * SEQ + ss + 8] = o3;
            } else {
                *(float2*)&C[(size_t)r * N + c] = make_float2(o0, o1);
                *(float2*)&C[(size_t)(r + 8) * N + c] = make_float2(o2, o3);
            }
        }
    }
}

// ---------------------------------------------------------------------------
// Fused Q+K+V projections: 320 flattened CTAs.
// [0,256): Q tiles (128x128, OMODE=2).  [256,288): K (128x64, OMODE=1).
// [288,320): V (128x64, transposed out, OMODE=3).
// ---------------------------------------------------------------------------
__global__ __launch_bounds__(256)
void gemm_qkv(const float* __restrict__ Aq, const float* __restrict__ Wqt,
              const float* __restrict__ bq, float* __restrict__ Cq,
              const float* __restrict__ Ak, const float* __restrict__ Wkt,
              const float* __restrict__ bk, float* __restrict__ Ck,
              const float* __restrict__ Av, const float* __restrict__ Wvt,
              const float* __restrict__ bv, float* __restrict__ Cv)
{
    const int blk = blockIdx.x;
    if (blk < 256) {
        gemm_body<128, 128, 32, 2>(Aq, Wqt, bq, Cq, D_MODEL, D_MODEL,
                                   (blk >> 3) * 128, (blk & 7) * 128);
    } else if (blk < 288) {
        gemm_body<128, 64, 16, 1>(Ak, Wkt, bk, Ck, DK, D_MODEL,
                                  (blk - 256) * 128, 0);
    } else {
        gemm_body<128, 64, 16, 3>(Av, Wvt, bv, Cv, DK, D_MODEL,
                                  (blk - 288) * 128, 0);
    }
}

__global__ __launch_bounds__(256)
void gemm_o(const float* __restrict__ A, const float* __restrict__ Wt,
            const float* __restrict__ bias, float* __restrict__ C)
{
    gemm_body<128, 128, 32, 0>(A, Wt, bias, C, D_MODEL, D_MODEL,
                               blockIdx.y * 128, blockIdx.x * 128);
}

#define GEMM_SMEM_128 ((2 * 128 * 36 + 2 * 128 * 36) * 4)   // 73728

// ---------------------------------------------------------------------------
// Flash attention (MQA, causal), 2 heads/CTA, merged MMA bursts, cp.async
// staging for Q, K and Vt (all pre-rounded/pre-scaled tf32 bits).
// ---------------------------------------------------------------------------
#define AS 68
#define ATTN_SMEM_TC ((4 * 64 + 128) * AS * 4)   // 104448 B

__global__ __launch_bounds__(256)
void attn_tc(const float* __restrict__ Q, const float* __restrict__ K,
             const float* __restrict__ Vt, float* __restrict__ Ctx)
{
    extern __shared__ unsigned smu[];
    const unsigned sb = (unsigned)__cvta_generic_to_shared(smu);
    unsigned* Ps = smu + 4 * 64 * AS;
    const unsigned ps_base = sb + (unsigned)(4 * 64 * AS * 4);

    const int t = threadIdx.x, lane = t & 31, w = t >> 5;
    const int hw = w & 3;
    const int gid = lane >> 2, tig = lane & 3;
    const int qt = (int)(gridDim.x - 1) - (int)blockIdx.x;  // long blocks first
    const int h = blockIdx.y * 2 + (w >> 2);
    const int b = blockIdx.z;

    const int m4 = lane >> 3, j8 = lane & 7;
    const unsigned a_loff = (unsigned)((((m4 & 1) * 8 + j8) * AS +
                                        (m4 >> 1) * 4) * 4);
    const unsigned b_loff = (unsigned)((((m4 >> 1) * 8 + j8) * AS +
                                        (m4 & 1) * 4) * 4);

    // ---- preloop: cp.async K0 (+K1), V0, and Q (both heads) ----
    {
        #pragma unroll
        for (int ld = 0; ld < 4; ++ld) {
            int i = t + 256 * ld;
            int row = i >> 4, c4 = (i & 15) * 4;
            unsigned so = (unsigned)(row * AS + c4) * 4u;
            cpa16(sb + so, K + ((size_t)(b * SEQ + row)) * DK + c4);
            if (qt >= 1)
                cpa16(sb + (64 * AS) * 4u + so,
                      K + ((size_t)(b * SEQ + 64 + row)) * DK + c4);
            cpa16(sb + (2 * 64 * AS) * 4u + so,
                  Vt + ((size_t)(b * DK + row)) * SEQ + c4);
        }
        #pragma unroll
        for (int ld = 0; ld < 8; ++ld) {
            int i = t + 256 * ld;
            int row = i >> 4, c4 = (i & 15) * 4;
            int hh = blockIdx.y * 2 + (row >> 6);
            int qrow = row & 63;
            cpa16(ps_base + (unsigned)(row * AS + c4) * 4u,
                  Q + ((size_t)(b * SEQ + qt * 64 + qrow)) * D_MODEL
                    + hh * DK + c4);
        }
        CP_COMMIT();
    }
    CP_WAIT0();
    __syncthreads();

    const unsigned ps_warp = ps_base + (unsigned)(16 * w * AS * 4);
    unsigned Qa[8][4];
    #pragma unroll
    for (int kf = 0; kf < 8; ++kf)
        ldsm4(Qa[kf], ps_warp + a_loff + kf * 32);

    float m0 = -INFINITY, m1 = -INFINITY, l0 = 0.0f, l1 = 0.0f;
    float O[8][4], S[8][4];
    #pragma unroll
    for (int nf = 0; nf < 8; ++nf)
        #pragma unroll
        for (int x = 0; x < 4; ++x) { O[nf][x] = 0.0f; S[nf][x] = 0.0f; }

    // ---- QK(0) from stage 0 ----
    #pragma unroll
    for (int kf = 0; kf < 8; ++kf) {
        #pragma unroll
        for (int nfp = 0; nfp < 4; ++nfp) {
            unsigned bb[4];
            ldsm4(bb, sb + (unsigned)(nfp * 16 * AS * 4) + b_loff + kf * 32);
            mma8(S[2 * nfp],     Qa[kf], bb[0], bb[1]);
            mma8(S[2 * nfp + 1], Qa[kf], bb[2], bb[3]);
        }
    }

    for (int j = 0; j <= qt; ++j) {
        CP_WAIT0();
        __syncthreads();

        // ---- prefetch K(j+2) -> stage j%2, V(j+1) -> stage (j+1)%2 ----
        {
            const unsigned ko = (unsigned)((j & 1) * 64 * AS) * 4u;
            const unsigned vo = (unsigned)((2 + ((j + 1) & 1)) * 64 * AS) * 4u;
            #pragma unroll
            for (int ld = 0; ld < 4; ++ld) {
                int i = t + 256 * ld;
                int row = i >> 4, c4 = (i & 15) * 4;
                unsigned so = (unsigned)(row * AS + c4) * 4u;
                if (j + 2 <= qt)
                    cpa16(sb + ko + so,
                          K + ((size_t)(b * SEQ + (j + 2) * 64 + row)) * DK + c4);
                if (j + 1 <= qt)
                    cpa16(sb + vo + so,
                          Vt + ((size_t)(b * DK + row)) * SEQ + (j + 1) * 64 + c4);
            }
            CP_COMMIT();
        }

        // ---- softmax on S (tile j) ----
        if (j == qt) {
            int qr = qt * 64 + 16 * hw + gid;
            #pragma unroll
            for (int nf = 0; nf < 8; ++nf) {
                int c0 = j * 64 + nf * 8 + 2 * tig;
                if (c0     > qr)     S[nf][0] = -INFINITY;
                if (c0 + 1 > qr)     S[nf][1] = -INFINITY;
                if (c0     > qr + 8) S[nf][2] = -INFINITY;
                if (c0 + 1 > qr + 8) S[nf][3] = -INFINITY;
            }
        }
        float mx0 = -INFINITY, mx1 = -INFINITY;
        #pragma unroll
        for (int nf = 0; nf < 8; ++nf) {
            mx0 = fmaxf(mx0, fmaxf(S[nf][0], S[nf][1]));
            mx1 = fmaxf(mx1, fmaxf(S[nf][2], S[nf][3]));
        }
        mx0 = fmaxf(mx0, __shfl_xor_sync(0xffffffffu, mx0, 1));
        mx0 = fmaxf(mx0, __shfl_xor_sync(0xffffffffu, mx0, 2));
        mx1 = fmaxf(mx1, __shfl_xor_sync(0xffffffffu, mx1, 1));
        mx1 = fmaxf(mx1, __shfl_xor_sync(0xffffffffu, mx1, 2));

        float mn0 = fmaxf(m0, mx0), mn1 = fmaxf(m1, mx1);
        float cr0 = __expf(m0 - mn0), cr1 = __expf(m1 - mn1);
        m0 = mn0; m1 = mn1;

        float rs0 = 0.0f, rs1 = 0.0f;
        #pragma unroll
        for (int nf = 0; nf < 8; ++nf) {
            S[nf][0] = __expf(S[nf][0] - mn0);
            S[nf][1] = __expf(S[nf][1] - mn0);
            S[nf][2] = __expf(S[nf][2] - mn1);
            S[nf][3] = __expf(S[nf][3] - mn1);
            rs0 += S[nf][0] + S[nf][1];
            rs1 += S[nf][2] + S[nf][3];
        }
        rs0 += __shfl_xor_sync(0xffffffffu, rs0, 1);
        rs0 += __shfl_xor_sync(0xffffffffu, rs0, 2);
        rs1 += __shfl_xor_sync(0xffffffffu, rs1, 1);
        rs1 += __shfl_xor_sync(0xffffffffu, rs1, 2);
        l0 = l0 * cr0 + rs0;
        l1 = l1 * cr1 + rs1;
        #pragma unroll
        for (int nf = 0; nf < 8; ++nf) {
            O[nf][0] *= cr0; O[nf][1] *= cr0;
            O[nf][2] *= cr1; O[nf][3] *= cr1;
        }

        // ---- P -> smem (warp-private rows), free S for tile j+1 ----
        const int pr = 16 * w + gid;
        #pragma unroll
        for (int nf = 0; nf < 8; ++nf) {
            int pc = nf * 8 + 2 * tig;
            *(uint2*)&Ps[pr * AS + pc] =
                make_uint2(f2tf(S[nf][0]), f2tf(S[nf][1]));
            *(uint2*)&Ps[(pr + 8) * AS + pc] =
                make_uint2(f2tf(S[nf][2]), f2tf(S[nf][3]));
            S[nf][0] = 0.0f; S[nf][1] = 0.0f; S[nf][2] = 0.0f; S[nf][3] = 0.0f;
        }
        __syncwarp();

        // ---- merged burst: QK(j+1) + PV(j) ----
        const unsigned ksb = sb + (unsigned)((((j + 1) & 1)) * 64 * AS * 4);
        const unsigned vtb = sb + (unsigned)((2 + (j & 1)) * 64 * AS * 4);
        if (j < qt) {
            #pragma unroll
            for (int kf = 0; kf < 8; ++kf) {
                unsigned pa[4];
                ldsm4(pa, ps_warp + a_loff + kf * 32);
                #pragma unroll
                for (int nfp = 0; nfp < 4; ++nfp) {
                    unsigned kb[4];
                    ldsm4(kb, ksb + (unsigned)(nfp * 16 * AS * 4) + b_loff
                              + kf * 32);
                    mma8(S[2 * nfp],     Qa[kf], kb[0], kb[1]);
                    mma8(S[2 * nfp + 1], Qa[kf], kb[2], kb[3]);
                }
                #pragma unroll
                for (int nfp = 0; nfp < 4; ++nfp) {
                    unsigned vb[4];
                    ldsm4(vb, vtb + (unsigned)(nfp * 16 * AS * 4) + b_loff
                              + kf * 32);
                    mma8(O[2 * nfp],     pa, vb[0], vb[1]);
                    mma8(O[2 * nfp + 1], pa, vb[2], vb[3]);
                }
            }
        } else {
            #pragma unroll
            for (int kf = 0; kf < 8; ++kf) {
                unsigned pa[4];
                ldsm4(pa, ps_warp + a_loff + kf * 32);
                #pragma unroll
                for (int nfp = 0; nfp < 4; ++nfp) {
                    unsigned vb[4];
                    ldsm4(vb, vtb + (unsigned)(nfp * 16 * AS * 4) + b_loff
                              + kf * 32);
                    mma8(O[2 * nfp],     pa, vb[0], vb[1]);
                    mma8(O[2 * nfp + 1], pa, vb[2], vb[3]);
                }
            }
        }
    }

    // ---- normalize + write context (tf32-rounded for the O projection) ----
    float inv0 = 1.0f / l0, inv1 = 1.0f / l1;
    int r0 = qt * 64 + 16 * hw + gid;
    #pragma unroll
    for (int nf = 0; nf < 8; ++nf) {
        int c = h * DK + nf * 8 + 2 * tig;
        *(float2*)&Ctx[((size_t)(b * SEQ + r0)) * D_MODEL + c] =
            make_float2(f2tff(O[nf][0] * inv0), f2tff(O[nf][1] * inv0));
        *(float2*)&Ctx[((size_t)(b * SEQ + r0 + 8)) * D_MODEL + c] =
            make_float2(f2tff(O[nf][2] * inv1), f2tff(O[nf][3] * inv1));
    }
}

// ---------------------------------------------------------------------------
// launch
// ---------------------------------------------------------------------------
extern "C" void kernel_launch(void* const* d_in, const int* in_sizes, int n_in,
                              void* d_out, int out_size)
{
    const float* iq = (const float*)d_in[0];
    const float* ik = (const float*)d_in[1];
    const float* iv = (const float*)d_in[2];
    const float* Wq = (const float*)d_in[3];
    const float* bq = (const float*)d_in[4];
    const float* Wk = (const float*)d_in[5];
    const float* bk = (const float*)d_in[6];
    const float* Wv = (const float*)d_in[7];
    const float* bv = (const float*)d_in[8];
    const float* Wo = (const float*)d_in[9];
    const float* bo = (const float*)d_in[10];
    float* out = (float*)d_out;

    float *pIQ, *pIK, *pIV, *pWqt, *pWkt, *pWvt, *pWot;
    float *pQ, *pK, *pVt, *pCtx;
    cudaGetSymbolAddress((void**)&pIQ,  g_IQr);
    cudaGetSymbolAddress((void**)&pIK,  g_IKr);
    cudaGetSymbolAddress((void**)&pIV,  g_IVr);
    cudaGetSymbolAddress((void**)&pWqt, g_Wqt);
    cudaGetSymbolAddress((void**)&pWkt, g_Wkt);
    cudaGetSymbolAddress((void**)&pWvt, g_Wvt);
    cudaGetSymbolAddress((void**)&pWot, g_Wot);
    cudaGetSymbolAddress((void**)&pQ,   g_Q);
    cudaGetSymbolAddress((void**)&pK,   g_K);
    cudaGetSymbolAddress((void**)&pVt,  g_Vt);
    cudaGetSymbolAddress((void**)&pCtx, g_Ctx);

    cudaFuncSetAttribute((const void*)gemm_qkv,
                         cudaFuncAttributeMaxDynamicSharedMemorySize,
                         GEMM_SMEM_128);
    cudaFuncSetAttribute((const void*)gemm_o,
                         cudaFuncAttributeMaxDynamicSharedMemorySize,
                         GEMM_SMEM_128);
    cudaFuncSetAttribute((const void*)attn_tc,
                         cudaFuncAttributeMaxDynamicSharedMemorySize,
                         ATTN_SMEM_TC);

    // ---- fused prep: round inputs + round/transpose all weights ----
    prep<<<NB_PREP, 256>>>(iq, ik, iv, pIQ, pIK, pIV,
                           Wq, pWqt, Wo, pWot, Wk, pWkt, Wv, pWvt);

    // ---- fused Q+K+V projections ----
    gemm_qkv<<<320, 256, GEMM_SMEM_128>>>(pIQ, pWqt, bq, pQ,
                                          pIK, pWkt, bk, pK,
                                          pIV, pWvt, bv, pVt);

    // ---- attention ----
    attn_tc<<<dim3(SEQ / 64, NHEADS / 2, BATCH), 256, ATTN_SMEM_TC>>>(
        pQ, pK, pVt, pCtx);

    // ---- output projection ----
    gemm_o<<<dim3(D_MODEL / 128, BS_TOK / 128), 256, GEMM_SMEM_128>>>(
        pCtx, pWot, bo, out);
}

// round 13
// speedup vs baseline: 1.0897x; 1.0360x over previous
#include <cuda_runtime.h>
#include <math.h>
#include <stdint.h>

#define D_MODEL 1024
#define NHEADS  16
#define DK      64
#define BATCH   2
#define SEQ     2048
#define BS_TOK  (BATCH * SEQ)   // 4096 tokens

// ---------------------------------------------------------------------------
// Scratch (device globals: no allocation allowed)
// ---------------------------------------------------------------------------
__device__ float g_IQr[BS_TOK * D_MODEL];   // tf32-rounded inputs
__device__ float g_IKr[BS_TOK * D_MODEL];
__device__ float g_IVr[BS_TOK * D_MODEL];
__device__ float g_Wqt[D_MODEL * D_MODEL];  // tf32-rounded, transposed [n][k]
__device__ float g_Wkt[DK * D_MODEL];
__device__ float g_Wvt[DK * D_MODEL];
__device__ float g_Wot[D_MODEL * D_MODEL];
__device__ float g_Q[BS_TOK * D_MODEL];     // pre-scaled (log2e/8) + rounded
__device__ float g_K[BS_TOK * DK];          // tf32-rounded, [b*S+s][dk]
__device__ float g_Vt[BS_TOK * DK];         // tf32-rounded, transposed [b][dv][s]
__device__ float g_Ctx[BS_TOK * D_MODEL];   // tf32-rounded

// logits scale: (1/sqrt(64)) * log2(e), folded into Q so softmax uses ex2
#define QSCALE 0.18033688011112042f

// ---------------------------------------------------------------------------
// tf32 / cp.async / ldmatrix helpers
// ---------------------------------------------------------------------------
__device__ __forceinline__ unsigned f2tf(float x) {
    unsigned r;
    asm("cvt.rna.tf32.f32 %0, %1;" : "=r"(r) : "f"(x));
    return r;
}
__device__ __forceinline__ float f2tff(float x) {
    return __uint_as_float(f2tf(x));
}
__device__ __forceinline__ float ex2(float x) {
    float r;
    asm("ex2.approx.ftz.f32 %0, %1;" : "=f"(r) : "f"(x));
    return r;
}

__device__ __forceinline__ void cpa16(unsigned dst, const void* src) {
    asm volatile("cp.async.cg.shared.global [%0], [%1], 16;"
                 :: "r"(dst), "l"(src));
}
#define CP_COMMIT() asm volatile("cp.async.commit_group;" ::: "memory")
#define CP_WAIT0()  asm volatile("cp.async.wait_group 0;" ::: "memory")

__device__ __forceinline__ void ldsm4(unsigned* r, unsigned addr) {
    asm volatile("ldmatrix.sync.aligned.m8n8.x4.shared.b16 {%0,%1,%2,%3}, [%4];"
                 : "=r"(r[0]), "=r"(r[1]), "=r"(r[2]), "=r"(r[3]) : "r"(addr));
}

__device__ __forceinline__ void mma8(float* c, const unsigned* a,
                                     unsigned b0, unsigned b1) {
    asm volatile(
        "mma.sync.aligned.m16n8k8.row.col.f32.tf32.tf32.f32 "
        "{%0,%1,%2,%3}, {%4,%5,%6,%7}, {%8,%9}, {%0,%1,%2,%3};"
        : "+f"(c[0]), "+f"(c[1]), "+f"(c[2]), "+f"(c[3])
        : "r"(a[0]), "r"(a[1]), "r"(a[2]), "r"(a[3]), "r"(b0), "r"(b1));
}

// ---------------------------------------------------------------------------
// Fused prep kernel: input rounding + all weight transposes, one launch.
// ---------------------------------------------------------------------------
#define NB_R3 768
#define NB_WB 1024
#define NB_WS 64
#define NB_PREP (NB_R3 + 2 * NB_WB + 2 * NB_WS)   // 2944

__device__ __forceinline__
void trW_body(const float* __restrict__ W, float* __restrict__ Wt,
              int K, int N, int bid, int tid)
{
    __shared__ float tl[32][33];
    const int nbx = N / 32;
    const int bx = (bid % nbx) * 32, by = (bid / nbx) * 32;
    const int tx = tid & 31, ty = tid >> 5;
    #pragma unroll
    for (int i = 0; i < 4; ++i)
        tl[ty + i * 8][tx] = f2tff(W[(size_t)(by + ty + i * 8) * N + bx + tx]);
    __syncthreads();
    #pragma unroll
    for (int i = 0; i < 4; ++i)
        Wt[(size_t)(bx + ty + i * 8) * K + by + tx] = tl[tx][ty + i * 8];
}

__global__ __launch_bounds__(256)
void prep(const float* __restrict__ iq, const float* __restrict__ ik,
          const float* __restrict__ iv, float* __restrict__ oq,
          float* __restrict__ ok, float* __restrict__ ov,
          const float* __restrict__ Wq, float* __restrict__ Wqt,
          const float* __restrict__ Wo, float* __restrict__ Wot,
          const float* __restrict__ Wk, float* __restrict__ Wkt,
          const float* __restrict__ Wv, float* __restrict__ Wvt)
{
    const int blk = blockIdx.x, tid = threadIdx.x;
    if (blk < NB_R3) {
        const int n4 = BS_TOK * D_MODEL / 4;
        for (int i = blk * 256 + tid; i < n4; i += NB_R3 * 256) {
            float4 v = ((const float4*)iq)[i];
            ((float4*)oq)[i] = make_float4(f2tff(v.x), f2tff(v.y),
                                           f2tff(v.z), f2tff(v.w));
            v = ((const float4*)ik)[i];
            ((float4*)ok)[i] = make_float4(f2tff(v.x), f2tff(v.y),
                                           f2tff(v.z), f2tff(v.w));
            v = ((const float4*)iv)[i];
            ((float4*)ov)[i] = make_float4(f2tff(v.x), f2tff(v.y),
                                           f2tff(v.z), f2tff(v.w));
        }
    } else if (blk < NB_R3 + NB_WB) {
        trW_body(Wq, Wqt, D_MODEL, D_MODEL, blk - NB_R3, tid);
    } else if (blk < NB_R3 + 2 * NB_WB) {
        trW_body(Wo, Wot, D_MODEL, D_MODEL, blk - NB_R3 - NB_WB, tid);
    } else if (blk < NB_R3 + 2 * NB_WB + NB_WS) {
        trW_body(Wk, Wkt, D_MODEL, DK, blk - NB_R3 - 2 * NB_WB, tid);
    } else {
        trW_body(Wv, Wvt, D_MODEL, DK, blk - NB_R3 - 2 * NB_WB - NB_WS, tid);
    }
}

// ---------------------------------------------------------------------------
// Tensor-core GEMM body, cp.async double-buffered, ldmatrix fragments.
// A [M,K] row-major (tf32 bits), Wt [N,K] row-major (tf32 bits).
// OMODE: 0 plain, 1 rtf, 2 rtf*QSCALE, 3 rtf + transposed V write.
// ---------------------------------------------------------------------------
template<int BM, int BN, int WN, int OMODE>
__device__ __forceinline__
void gemm_body(const float* __restrict__ A, const float* __restrict__ Wt,
               const float* __restrict__ bias, float* __restrict__ C,
               int N, int K, int m0, int n0)
{
    constexpr int ASTR = 36;
    constexpr int ABUF = BM * ASTR;
    constexpr int BBUF = BN * ASTR;
    constexpr int NF = WN / 8;
    constexpr int NWC = BN / WN;
    constexpr int ACH = BM / 32;
    constexpr int BCH = BN / 32;
    extern __shared__ __align__(1024) unsigned smg[];
    const unsigned sb = (unsigned)__cvta_generic_to_shared(smg);

    const int t = threadIdx.x, lane = t & 31, wp = t >> 5;
    const int wm0 = (wp / NWC) * 64, wn0 = (wp % NWC) * WN;
    const int gid = lane >> 2, tig = lane & 3;

    const int m4 = lane >> 3, j8 = lane & 7;
    const unsigned a_loff = (unsigned)((((m4 & 1) * 8 + j8) * ASTR +
                                        (m4 >> 1) * 4) * 4);
    const unsigned b_loff = (unsigned)((((m4 >> 1) * 8 + j8) * ASTR +
                                        (m4 & 1) * 4) * 4);

    #pragma unroll
    for (int i = 0; i < ACH; ++i) {
        int idx = t + 256 * i;
        int r = idx >> 3, c4 = (idx & 7) * 4;
        cpa16(sb + (unsigned)((r * ASTR + c4) * 4),
              A + (size_t)(m0 + r) * K + c4);
    }
    #pragma unroll
    for (int i = 0; i < BCH; ++i) {
        int idx = t + 256 * i;
        int r = idx >> 3, c4 = (idx & 7) * 4;
        cpa16(sb + (unsigned)((2 * ABUF + r * ASTR + c4) * 4),
              Wt + (size_t)(n0 + r) * K + c4);
    }
    CP_COMMIT();

    float acc[4][NF][4];
    #pragma unroll
    for (int mi = 0; mi < 4; ++mi)
        #pragma unroll
        for (int ni = 0; ni < NF; ++ni)
            #pragma unroll
            for (int x = 0; x < 4; ++x) acc[mi][ni][x] = 0.0f;

    int cur = 0;
    for (int k0 = 0; k0 < K; k0 += 32) {
        CP_WAIT0();
        __syncthreads();

        if (k0 + 32 < K) {
            const unsigned ao = (unsigned)((cur ^ 1) * ABUF * 4);
            const unsigned bo = (unsigned)((2 * ABUF + (cur ^ 1) * BBUF) * 4);
            #pragma unroll
            for (int i = 0; i < ACH; ++i) {
                int idx = t + 256 * i;
                int r = idx >> 3, c4 = (idx & 7) * 4;
                cpa16(sb + ao + (unsigned)((r * ASTR + c4) * 4),
                      A + (size_t)(m0 + r) * K + k0 + 32 + c4);
            }
            #pragma unroll
            for (int i = 0; i < BCH; ++i) {
                int idx = t + 256 * i;
                int r = idx >> 3, c4 = (idx & 7) * 4;
                cpa16(sb + bo + (unsigned)((r * ASTR + c4) * 4),
                      Wt + (size_t)(n0 + r) * K + k0 + 32 + c4);
            }
            CP_COMMIT();
        }

        const unsigned asb = sb + (unsigned)(cur * ABUF * 4) +
                             (unsigned)(wm0 * ASTR * 4) + a_loff;
        const unsigned bsb = sb + (unsigned)((2 * ABUF + cur * BBUF) * 4) +
                             (unsigned)(wn0 * ASTR * 4) + b_loff;

        #pragma unroll
        for (int kk = 0; kk < 4; ++kk) {
            unsigned a[4][4];
            #pragma unroll
            for (int mi = 0; mi < 4; ++mi)
                ldsm4(a[mi], asb + (unsigned)(mi * 16 * ASTR * 4 + kk * 32));
            #pragma unroll
            for (int nfp = 0; nfp < NF / 2; ++nfp) {
                unsigned bb[4];
                ldsm4(bb, bsb + (unsigned)(nfp * 16 * ASTR * 4 + kk * 32));
                #pragma unroll
                for (int mi = 0; mi < 4; ++mi) {
                    mma8(acc[mi][2 * nfp],     a[mi], bb[0], bb[1]);
                    mma8(acc[mi][2 * nfp + 1], a[mi], bb[2], bb[3]);
                }
            }
        }
        cur ^= 1;
    }

    #pragma unroll
    for (int mi = 0; mi < 4; ++mi) {
        int r = m0 + wm0 + mi * 16 + gid;
        #pragma unroll
        for (int ni = 0; ni < NF; ++ni) {
            int c = n0 + wn0 + ni * 8 + 2 * tig;
            float bb0 = bias[c], bb1 = bias[c + 1];
            float o0 = acc[mi][ni][0] + bb0, o1 = acc[mi][ni][1] + bb1;
            float o2 = acc[mi][ni][2] + bb0, o3 = acc[mi][ni][3] + bb1;
            if (OMODE == 2) {
                o0 = f2tff(QSCALE * o0); o1 = f2tff(QSCALE * o1);
                o2 = f2tff(QSCALE * o2); o3 = f2tff(QSCALE * o3);
            } else if (OMODE == 1 || OMODE == 3) {
                o0 = f2tff(o0); o1 = f2tff(o1);
                o2 = f2tff(o2); o3 = f2tff(o3);
            }
            if (OMODE == 3) {
                int bb_ = r >> 11, ss = r & (SEQ - 1);
                C[((size_t)(bb_ * DK + c))     * SEQ + ss]     = o0;
                C[((size_t)(bb_ * DK + c + 1)) * SEQ + ss]     = o1;
                C[((size_t)(bb_ * DK + c))     * SEQ + ss + 8] = o2;
                C[((size_t)(bb_ * DK + c + 1)) * SEQ + ss + 8] = o3;
            } else {
                *(float2*)&C[(size_t)r * N + c] = make_float2(o0, o1);
                *(float2*)&C[(size_t)(r + 8) * N + c] = make_float2(o2, o3);
            }
        }
    }
}

// ---------------------------------------------------------------------------
// Fused Q+K+V projections: 288 CTAs = exactly one wave at 2 CTAs/SM.
// [0,256): Q tiles (128x128, OMODE=2).
// [256,288): K tile then V tile (each 128x64), sequential in one CTA.
// ---------------------------------------------------------------------------
__global__ __launch_bounds__(256)
void gemm_qkv(const float* __restrict__ Aq, const float* __restrict__ Wqt,
              const float* __restrict__ bq, float* __restrict__ Cq,
              const float* __restrict__ Ak, const float* __restrict__ Wkt,
              const float* __restrict__ bk, float* __restrict__ Ck,
              const float* __restrict__ Av, const float* __restrict__ Wvt,
              const float* __restrict__ bv, float* __restrict__ Cv)
{
    const int blk = blockIdx.x;
    if (blk < 256) {
        gemm_body<128, 128, 32, 2>(Aq, Wqt, bq, Cq, D_MODEL, D_MODEL,
                                   (blk >> 3) * 128, (blk & 7) * 128);
    } else {
        const int kb = blk - 256;   // 0..31
        gemm_body<128, 64, 16, 1>(Ak, Wkt, bk, Ck, DK, D_MODEL, kb * 128, 0);
        __syncthreads();            // protect smem reuse between the two GEMMs
        gemm_body<128, 64, 16, 3>(Av, Wvt, bv, Cv, DK, D_MODEL, kb * 128, 0);
    }
}

__global__ __launch_bounds__(256)
void gemm_o(const float* __restrict__ A, const float* __restrict__ Wt,
            const float* __restrict__ bias, float* __restrict__ C)
{
    gemm_body<128, 128, 32, 0>(A, Wt, bias, C, D_MODEL, D_MODEL,
                               blockIdx.y * 128, blockIdx.x * 128);
}

#define GEMM_SMEM_128 ((2 * 128 * 36 + 2 * 128 * 36) * 4)   // 73728

// ---------------------------------------------------------------------------
// Flash attention (MQA, causal), 2 heads/CTA, merged MMA bursts, cp.async
// staging; softmax in log2 domain (Q pre-scaled by log2e/8, ex2.approx).
// ---------------------------------------------------------------------------
#define AS 68
#define ATTN_SMEM_TC ((4 * 64 + 128) * AS * 4)   // 104448 B

__global__ __launch_bounds__(256)
void attn_tc(const float* __restrict__ Q, const float* __restrict__ K,
             const float* __restrict__ Vt, float* __restrict__ Ctx)
{
    extern __shared__ __align__(1024) unsigned smu[];
    const unsigned sb = (unsigned)__cvta_generic_to_shared(smu);
    unsigned* Ps = smu + 4 * 64 * AS;
    const unsigned ps_base = sb + (unsigned)(4 * 64 * AS * 4);

    const int t = threadIdx.x, lane = t & 31, w = t >> 5;
    const int hw = w & 3;
    const int gid = lane >> 2, tig = lane & 3;
    const int qt = (int)(gridDim.x - 1) - (int)blockIdx.x;  // long blocks first
    const int h = blockIdx.y * 2 + (w >> 2);
    const int b = blockIdx.z;

    const int m4 = lane >> 3, j8 = lane & 7;
    const unsigned a_loff = (unsigned)((((m4 & 1) * 8 + j8) * AS +
                                        (m4 >> 1) * 4) * 4);
    const unsigned b_loff = (unsigned)((((m4 >> 1) * 8 + j8) * AS +
                                        (m4 & 1) * 4) * 4);

    // ---- preloop: cp.async K0 (+K1), V0, and Q (both heads) ----
    {
        #pragma unroll
        for (int ld = 0; ld < 4; ++ld) {
            int i = t + 256 * ld;
            int row = i >> 4, c4 = (i & 15) * 4;
            unsigned so = (unsigned)(row * AS + c4) * 4u;
            cpa16(sb + so, K + ((size_t)(b * SEQ + row)) * DK + c4);
            if (qt >= 1)
                cpa16(sb + (64 * AS) * 4u + so,
                      K + ((size_t)(b * SEQ + 64 + row)) * DK + c4);
            cpa16(sb + (2 * 64 * AS) * 4u + so,
                  Vt + ((size_t)(b * DK + row)) * SEQ + c4);
        }
        #pragma unroll
        for (int ld = 0; ld < 8; ++ld) {
            int i = t + 256 * ld;
            int row = i >> 4, c4 = (i & 15) * 4;
            int hh = blockIdx.y * 2 + (row >> 6);
            int qrow = row & 63;
            cpa16(ps_base + (unsigned)(row * AS + c4) * 4u,
                  Q + ((size_t)(b * SEQ + qt * 64 + qrow)) * D_MODEL
                    + hh * DK + c4);
        }
        CP_COMMIT();
    }
    CP_WAIT0();
    __syncthreads();

    const unsigned ps_warp = ps_base + (unsigned)(16 * w * AS * 4);
    unsigned Qa[8][4];
    #pragma unroll
    for (int kf = 0; kf < 8; ++kf)
        ldsm4(Qa[kf], ps_warp + a_loff + kf * 32);

    float m0 = -INFINITY, m1 = -INFINITY, l0 = 0.0f, l1 = 0.0f;
    float O[8][4], S[8][4];
    #pragma unroll
    for (int nf = 0; nf < 8; ++nf)
        #pragma unroll
        for (int x = 0; x < 4; ++x) { O[nf][x] = 0.0f; S[nf][x] = 0.0f; }

    // ---- QK(0) from stage 0 ----
    #pragma unroll
    for (int kf = 0; kf < 8; ++kf) {
        #pragma unroll
        for (int nfp = 0; nfp < 4; ++nfp) {
            unsigned bb[4];
            ldsm4(bb, sb + (unsigned)(nfp * 16 * AS * 4) + b_loff + kf * 32);
            mma8(S[2 * nfp],     Qa[kf], bb[0], bb[1]);
            mma8(S[2 * nfp + 1], Qa[kf], bb[2], bb[3]);
        }
    }

    for (int j = 0; j <= qt; ++j) {
        CP_WAIT0();
        __syncthreads();

        // ---- prefetch K(j+2) -> stage j%2, V(j+1) -> stage (j+1)%2 ----
        {
            const unsigned ko = (unsigned)((j & 1) * 64 * AS) * 4u;
            const unsigned vo = (unsigned)((2 + ((j + 1) & 1)) * 64 * AS) * 4u;
            #pragma unroll
            for (int ld = 0; ld < 4; ++ld) {
                int i = t + 256 * ld;
                int row = i >> 4, c4 = (i & 15) * 4;
                unsigned so = (unsigned)(row * AS + c4) * 4u;
                if (j + 2 <= qt)
                    cpa16(sb + ko + so,
                          K + ((size_t)(b * SEQ + (j + 2) * 64 + row)) * DK + c4);
                if (j + 1 <= qt)
                    cpa16(sb + vo + so,
                          Vt + ((size_t)(b * DK + row)) * SEQ + (j + 1) * 64 + c4);
            }
            CP_COMMIT();
        }

        // ---- softmax on S (tile j), log2 domain ----
        if (j == qt) {
            int qr = qt * 64 + 16 * hw + gid;
            #pragma unroll
            for (int nf = 0; nf < 8; ++nf) {
                int c0 = j * 64 + nf * 8 + 2 * tig;
                if (c0     > qr)     S[nf][0] = -INFINITY;
                if (c0 + 1 > qr)     S[nf][1] = -INFINITY;
                if (c0     > qr + 8) S[nf][2] = -INFINITY;
                if (c0 + 1 > qr + 8) S[nf][3] = -INFINITY;
            }
        }
        float mx0 = -INFINITY, mx1 = -INFINITY;
        #pragma unroll
        for (int nf = 0; nf < 8; ++nf) {
            mx0 = fmaxf(mx0, fmaxf(S[nf][0], S[nf][1]));
            mx1 = fmaxf(mx1, fmaxf(S[nf][2], S[nf][3]));
        }
        mx0 = fmaxf(mx0, __shfl_xor_sync(0xffffffffu, mx0, 1));
        mx0 = fmaxf(mx0, __shfl_xor_sync(0xffffffffu, mx0, 2));
        mx1 = fmaxf(mx1, __shfl_xor_sync(0xffffffffu, mx1, 1));
        mx1 = fmaxf(mx1, __shfl_xor_sync(0xffffffffu, mx1, 2));

        float mn0 = fmaxf(m0, mx0), mn1 = fmaxf(m1, mx1);
        float cr0 = ex2(m0 - mn0), cr1 = ex2(m1 - mn1);
        m0 = mn0; m1 = mn1;

        float rs0 = 0.0f, rs1 = 0.0f;
        #pragma unroll
        for (int nf = 0; nf < 8; ++nf) {
            S[nf][0] = ex2(S[nf][0] - mn0);
            S[nf][1] = ex2(S[nf][1] - mn0);
            S[nf][2] = ex2(S[nf][2] - mn1);
            S[nf][3] = ex2(S[nf][3] - mn1);
            rs0 += S[nf][0] + S[nf][1];
            rs1 += S[nf][2] + S[nf][3];
        }
        rs0 += __shfl_xor_sync(0xffffffffu, rs0, 1);
        rs0 += __shfl_xor_sync(0xffffffffu, rs0, 2);
        rs1 += __shfl_xor_sync(0xffffffffu, rs1, 1);
        rs1 += __shfl_xor_sync(0xffffffffu, rs1, 2);
        l0 = l0 * cr0 + rs0;
        l1 = l1 * cr1 + rs1;
        #pragma unroll
        for (int nf = 0; nf < 8; ++nf) {
            O[nf][0] *= cr0; O[nf][1] *= cr0;
            O[nf][2] *= cr1; O[nf][3] *= cr1;
        }

        // ---- P -> smem (warp-private rows), free S for tile j+1 ----
        const int pr = 16 * w + gid;
        #pragma unroll
        for (int nf = 0; nf < 8; ++nf) {
            int pc = nf * 8 + 2 * tig;
            *(uint2*)&Ps[pr * AS + pc] =
                make_uint2(f2tf(S[nf][0]), f2tf(S[nf][1]));
            *(uint2*)&Ps[(pr + 8) * AS + pc] =
                make_uint2(f2tf(S[nf][2]), f2tf(S[nf][3]));
            S[nf][0] = 0.0f; S[nf][1] = 0.0f; S[nf][2] = 0.0f; S[nf][3] = 0.0f;
        }
        __syncwarp();

        // ---- merged burst: QK(j+1) + PV(j) ----
        const unsigned ksb = sb + (unsigned)((((j + 1) & 1)) * 64 * AS * 4);
        const unsigned vtb = sb + (unsigned)((2 + (j & 1)) * 64 * AS * 4);
        if (j < qt) {
            #pragma unroll
            for (int kf = 0; kf < 8; ++kf) {
                unsigned pa[4];
                ldsm4(pa, ps_warp + a_loff + kf * 32);
                #pragma unroll
                for (int nfp = 0; nfp < 4; ++nfp) {
                    unsigned kb[4];
                    ldsm4(kb, ksb + (unsigned)(nfp * 16 * AS * 4) + b_loff
                              + kf * 32);
                    mma8(S[2 * nfp],     Qa[kf], kb[0], kb[1]);
                    mma8(S[2 * nfp + 1], Qa[kf], kb[2], kb[3]);
                }
                #pragma unroll
                for (int nfp = 0; nfp < 4; ++nfp) {
                    unsigned vb[4];
                    ldsm4(vb, vtb + (unsigned)(nfp * 16 * AS * 4) + b_loff
                              + kf * 32);
                    mma8(O[2 * nfp],     pa, vb[0], vb[1]);
                    mma8(O[2 * nfp + 1], pa, vb[2], vb[3]);
                }
            }
        } else {
            #pragma unroll
            for (int kf = 0; kf < 8; ++kf) {
                unsigned pa[4];
                ldsm4(pa, ps_warp + a_loff + kf * 32);
                #pragma unroll
                for (int nfp = 0; nfp < 4; ++nfp) {
                    unsigned vb[4];
                    ldsm4(vb, vtb + (unsigned)(nfp * 16 * AS * 4) + b_loff
                              + kf * 32);
                    mma8(O[2 * nfp],     pa, vb[0], vb[1]);
                    mma8(O[2 * nfp + 1], pa, vb[2], vb[3]);
                }
            }
        }
    }

    // ---- normalize + write context (tf32-rounded for the O projection) ----
    float inv0 = 1.0f / l0, inv1 = 1.0f / l1;
    int r0 = qt * 64 + 16 * hw + gid;
    #pragma unroll
    for (int nf = 0; nf < 8; ++nf) {
        int c = h * DK + nf * 8 + 2 * tig;
        *(float2*)&Ctx[((size_t)(b * SEQ + r0)) * D_MODEL + c] =
            make_float2(f2tff(O[nf][0] * inv0), f2tff(O[nf][1] * inv0));
        *(float2*)&Ctx[((size_t)(b * SEQ + r0 + 8)) * D_MODEL + c] =
            make_float2(f2tff(O[nf][2] * inv1), f2tff(O[nf][3] * inv1));
    }
}

// ---------------------------------------------------------------------------
// launch
// ---------------------------------------------------------------------------
extern "C" void kernel_launch(void* const* d_in, const int* in_sizes, int n_in,
                              void* d_out, int out_size)
{
    const float* iq = (const float*)d_in[0];
    const float* ik = (const float*)d_in[1];
    const float* iv = (const float*)d_in[2];
    const float* Wq = (const float*)d_in[3];
    const float* bq = (const float*)d_in[4];
    const float* Wk = (const float*)d_in[5];
    const float* bk = (const float*)d_in[6];
    const float* Wv = (const float*)d_in[7];
    const float* bv = (const float*)d_in[8];
    const float* Wo = (const float*)d_in[9];
    const float* bo = (const float*)d_in[10];
    float* out = (float*)d_out;

    float *pIQ, *pIK, *pIV, *pWqt, *pWkt, *pWvt, *pWot;
    float *pQ, *pK, *pVt, *pCtx;
    cudaGetSymbolAddress((void**)&pIQ,  g_IQr);
    cudaGetSymbolAddress((void**)&pIK,  g_IKr);
    cudaGetSymbolAddress((void**)&pIV,  g_IVr);
    cudaGetSymbolAddress((void**)&pWqt, g_Wqt);
    cudaGetSymbolAddress((void**)&pWkt, g_Wkt);
    cudaGetSymbolAddress((void**)&pWvt, g_Wvt);
    cudaGetSymbolAddress((void**)&pWot, g_Wot);
    cudaGetSymbolAddress((void**)&pQ,   g_Q);
    cudaGetSymbolAddress((void**)&pK,   g_K);
    cudaGetSymbolAddress((void**)&pVt,  g_Vt);
    cudaGetSymbolAddress((void**)&pCtx, g_Ctx);

    cudaFuncSetAttribute((const void*)gemm_qkv,
                         cudaFuncAttributeMaxDynamicSharedMemorySize,
                         GEMM_SMEM_128);
    cudaFuncSetAttribute((const void*)gemm_o,
                         cudaFuncAttributeMaxDynamicSharedMemorySize,
                         GEMM_SMEM_128);
    cudaFuncSetAttribute((const void*)attn_tc,
                         cudaFuncAttributeMaxDynamicSharedMemorySize,
                         ATTN_SMEM_TC);

    // ---- fused prep: round inputs + round/transpose all weights ----
    prep<<<NB_PREP, 256>>>(iq, ik, iv, pIQ, pIK, pIV,
                           Wq, pWqt, Wo, pWot, Wk, pWkt, Wv, pWvt);

    // ---- fused Q+K+V projections (288 CTAs = one wave) ----
    gemm_qkv<<<288, 256, GEMM_SMEM_128>>>(pIQ, pWqt, bq, pQ,
                                          pIK, pWkt, bk, pK,
                                          pIV, pWvt, bv, pVt);

    // ---- attention ----
    attn_tc<<<dim3(SEQ / 64, NHEADS / 2, BATCH), 256, ATTN_SMEM_TC>>>(
        pQ, pK, pVt, pCtx);

    // ---- output projection ----
    gemm_o<<<dim3(D_MODEL / 128, BS_TOK / 128), 256, GEMM_SMEM_128>>>(
        pCtx, pWot, bo, out);
}